// round 13
// baseline (speedup 1.0000x reference)
#include <cuda_runtime.h>
#include <cstdint>
#include <cstddef>

#define BB   32
#define NN   1024
#define DIMV 512
#define HH   8
#define KDV  64
#define DV   256
#define DHV  2048
#define QKVV 3072

// ---------------- scratch (device globals; allocation-free) ----------------
__device__ float g_xn[(size_t)BB * NN * DIMV];        //  64 MB
__device__ float g_qkv[(size_t)BB * NN * QKVV];       // 384 MB
__device__ float g_attn[(size_t)BB * HH * NN * NN];   //   1 GB: P = exp(logits)
__device__ float g_av[(size_t)BB * NN * DHV];         // 256 MB (b, q, h, d)
__device__ float g_biasmat[(size_t)HH * NN * NN];     //  32 MB (h, q, k)

// ---------------- helpers ----------------
__device__ __forceinline__ uint32_t f2tf32(float x) {
    uint32_t r;
    asm("cvt.rna.tf32.f32 %0, %1;" : "=r"(r) : "f"(x));
    return r;
}

__device__ __forceinline__ void mma_tf32(float c[4], const uint32_t a[4],
                                         const uint32_t b[2]) {
    asm volatile(
        "mma.sync.aligned.m16n8k8.row.col.f32.tf32.tf32.f32 "
        "{%0,%1,%2,%3}, {%4,%5,%6,%7}, {%8,%9}, {%0,%1,%2,%3};\n"
        : "+f"(c[0]), "+f"(c[1]), "+f"(c[2]), "+f"(c[3])
        : "r"(a[0]), "r"(a[1]), "r"(a[2]), "r"(a[3]), "r"(b[0]), "r"(b[1]));
}

__device__ __forceinline__ void cp16(void* smem_dst, const void* gsrc) {
    uint32_t d = (uint32_t)__cvta_generic_to_shared(smem_dst);
    asm volatile("cp.async.cg.shared.global [%0], [%1], 16;\n"
                 :: "r"(d), "l"(gsrc));
}
#define CP_COMMIT() asm volatile("cp.async.commit_group;\n" ::: "memory")
#define CP_WAIT1()  asm volatile("cp.async.wait_group 1;\n" ::: "memory")

// ---------------- LayerNorm ----------------
__global__ void __launch_bounds__(128)
ln_kernel(const float* __restrict__ x, const float* __restrict__ gamma,
          const float* __restrict__ beta) {
    const int row = blockIdx.x;
    const int t = threadIdx.x;
    const float4 v = reinterpret_cast<const float4*>(x)[(size_t)row * (DIMV / 4) + t];
    float s  = v.x + v.y + v.z + v.w;
    float sq = v.x * v.x + v.y * v.y + v.z * v.z + v.w * v.w;
    #pragma unroll
    for (int o = 16; o > 0; o >>= 1) {
        s  += __shfl_xor_sync(0xffffffffu, s, o);
        sq += __shfl_xor_sync(0xffffffffu, sq, o);
    }
    __shared__ float ss[4], ssq[4];
    const int w = t >> 5, l = t & 31;
    if (l == 0) { ss[w] = s; ssq[w] = sq; }
    __syncthreads();
    if (t == 0) {
        float S  = ss[0] + ss[1] + ss[2] + ss[3];
        float SQ = ssq[0] + ssq[1] + ssq[2] + ssq[3];
        float mu = S * (1.0f / DIMV);
        float var = SQ * (1.0f / DIMV) - mu * mu;
        ss[0]  = mu;
        ssq[0] = rsqrtf(var + 1e-5f);
    }
    __syncthreads();
    const float mu = ss[0], rstd = ssq[0];
    const float4 g  = reinterpret_cast<const float4*>(gamma)[t];
    const float4 bt = reinterpret_cast<const float4*>(beta)[t];
    float4 o;
    o.x = (v.x - mu) * rstd * g.x + bt.x;
    o.y = (v.y - mu) * rstd * g.y + bt.y;
    o.z = (v.z - mu) * rstd * g.z + bt.z;
    o.w = (v.w - mu) * rstd * g.w + bt.w;
    reinterpret_cast<float4*>(g_xn)[(size_t)row * (DIMV / 4) + t] = o;
}

// ---------------- dense bias matrix ----------------
__global__ void __launch_bounds__(256)
biasmat_kernel(const float* __restrict__ biases, const int* __restrict__ bidx) {
    const int h = blockIdx.y;
    const size_t i = (size_t)blockIdx.x * 256 + threadIdx.x;
    g_biasmat[(size_t)h * NN * NN + i] = biases[h * 1024 + bidx[i]];
}

// ---------------- unified tf32 tensor-core GEMM, cp.async pipelined ----------
// Tile BM=128, BN=128, BK=32; 256 threads, 8 warps (4M x 2N), warp tile 32x64.
// 2-stage cp.async double buffer; fp32 in smem; tf32 cvt at fragment load.
// MODE 0: g_xn @ qkv_w + qkv_b -> g_qkv
// MODE 1: per bz: P = exp(Q @ K^T * 0.125 + biasmat) -> g_attn  (B = K rows)
// MODE 2: per bz: (P @ V) / rowsum(P) -> g_av   (denominator via side-sum)
// MODE 3: g_av @ proj_w + proj_b -> out
#define AS_ELEMS (128 * 36)
#define STAGE_ELEMS (AS_ELEMS + 4608)
#define MM_SMEM (2 * STAGE_ELEMS * 4)

template<int MODE>
__global__ void __launch_bounds__(256, 2)
mm_tf32(const float* __restrict__ Barg, float* __restrict__ Carg,
        const float* __restrict__ biasv) {
    constexpr int  LDA    = (MODE == 0) ? DIMV : (MODE == 1) ? QKVV
                          : (MODE == 2) ? NN   : DHV;
    constexpr int  LDB    = (MODE == 0) ? QKVV : (MODE == 1) ? QKVV
                          : (MODE == 2) ? QKVV : DIMV;
    constexpr int  LDC    = (MODE == 0) ? QKVV : (MODE == 1) ? NN
                          : (MODE == 2) ? DHV  : DIMV;
    constexpr int  KDIM   = (MODE == 0) ? DIMV : (MODE == 1) ? KDV
                          : (MODE == 2) ? NN   : DHV;
    constexpr bool TRANSB = (MODE == 1);
    constexpr int  NK     = KDIM / 32;

    extern __shared__ float sm[];

    const int tid = threadIdx.x;
    const int m0 = blockIdx.y * 128;
    const int n0 = blockIdx.x * 128;

    const float* Ap;
    const float* Bp;
    float* Cp;
    const float* bmp = nullptr;
    if (MODE == 0) {
        Ap = g_xn; Bp = Barg; Cp = g_qkv;
    } else if (MODE == 1) {
        const int bz = blockIdx.z, b = bz >> 3, h = bz & 7;
        Ap = g_qkv + (size_t)b * NN * QKVV + h * 384;          // Q
        Bp = g_qkv + (size_t)b * NN * QKVV + h * 384 + 64;     // K (rows)
        Cp = g_attn + (size_t)bz * NN * NN;
        bmp = g_biasmat + (size_t)h * NN * NN;
    } else if (MODE == 2) {
        const int bz = blockIdx.z, b = bz >> 3, h = bz & 7;
        Ap = g_attn + (size_t)bz * NN * NN;
        Bp = g_qkv + (size_t)b * NN * QKVV + h * 384 + 128;    // V
        Cp = g_av + (size_t)b * NN * DHV + h * DV;
    } else {
        Ap = g_av; Bp = Barg; Cp = Carg;
    }

    const int wid = tid >> 5, lane = tid & 31;
    const int wm = wid >> 1, wn = wid & 1;
    const int grp = lane >> 2, qd = lane & 3;

    const int ar = tid >> 3, ac = (tid & 7) * 4;
    const int br_n = tid >> 5, bc_n = (tid & 31) * 4;
    const int br_t = tid >> 3, bc_t = (tid & 7) * 4;

    auto issue_tile = [&](int kt) {
        const int stg = kt & 1;
        float* As = sm + stg * STAGE_ELEMS;
        float* Bs = As + AS_ELEMS;
        const int k0 = kt * 32;
        #pragma unroll
        for (int i = 0; i < 4; ++i) {
            const int r = ar + i * 32;
            cp16(&As[r * 36 + ac], &Ap[(size_t)(m0 + r) * LDA + k0 + ac]);
        }
        if (TRANSB) {
            #pragma unroll
            for (int i = 0; i < 4; ++i) {
                const int r = br_t + i * 32;
                cp16(&Bs[r * 36 + bc_t], &Bp[(size_t)(n0 + r) * LDB + k0 + bc_t]);
            }
        } else {
            #pragma unroll
            for (int i = 0; i < 4; ++i) {
                const int r = br_n + i * 8;
                cp16(&Bs[r * 136 + bc_n], &Bp[(size_t)(k0 + r) * LDB + n0 + bc_n]);
            }
        }
    };

    float acc[2][8][4] = {};
    float lsum[2][2] = {};            // MODE 2: row partial sums of P

    issue_tile(0); CP_COMMIT();
    if (NK > 1) issue_tile(1);
    CP_COMMIT();

    for (int kt = 0; kt < NK; ++kt) {
        CP_WAIT1();
        __syncthreads();
        const float* As = sm + (kt & 1) * STAGE_ELEMS;
        const float* Bs = As + AS_ELEMS;
        #pragma unroll
        for (int ks = 0; ks < 4; ++ks) {
            const int kc = ks * 8 + qd;
            uint32_t af[2][4];
            #pragma unroll
            for (int mt = 0; mt < 2; ++mt) {
                const int mr = wm * 32 + mt * 16 + grp;
                const float a0 = As[mr * 36 + kc];
                const float a1 = As[(mr + 8) * 36 + kc];
                const float a2 = As[mr * 36 + kc + 4];
                const float a3 = As[(mr + 8) * 36 + kc + 4];
                af[mt][0] = f2tf32(a0);
                af[mt][1] = f2tf32(a1);
                af[mt][2] = f2tf32(a2);
                af[mt][3] = f2tf32(a3);
                if (MODE == 2) {
                    lsum[mt][0] += a0 + a2;   // row mr
                    lsum[mt][1] += a1 + a3;   // row mr+8
                }
            }
            uint32_t bf[8][2];
            #pragma unroll
            for (int nt = 0; nt < 8; ++nt) {
                const int nc = wn * 64 + nt * 8 + grp;
                if (TRANSB) {
                    bf[nt][0] = f2tf32(Bs[nc * 36 + kc]);
                    bf[nt][1] = f2tf32(Bs[nc * 36 + kc + 4]);
                } else {
                    bf[nt][0] = f2tf32(Bs[kc * 136 + nc]);
                    bf[nt][1] = f2tf32(Bs[(kc + 4) * 136 + nc]);
                }
            }
            #pragma unroll
            for (int mt = 0; mt < 2; ++mt)
                #pragma unroll
                for (int nt = 0; nt < 8; ++nt)
                    mma_tf32(acc[mt][nt], af[mt], bf[nt]);
        }
        __syncthreads();
        if (kt + 2 < NK) issue_tile(kt + 2);
        CP_COMMIT();
    }

    // MODE 2: complete row sums across the quad (qd 0..3 cover all 32 cols/BK)
    float inv[2][2];
    if (MODE == 2) {
        #pragma unroll
        for (int mt = 0; mt < 2; ++mt)
            #pragma unroll
            for (int j = 0; j < 2; ++j) {
                float s = lsum[mt][j];
                s += __shfl_xor_sync(0xffffffffu, s, 1);
                s += __shfl_xor_sync(0xffffffffu, s, 2);
                inv[mt][j] = 1.0f / s;
            }
    }

    // --- epilogue ---
    #pragma unroll
    for (int mt = 0; mt < 2; ++mt) {
        #pragma unroll
        for (int nt = 0; nt < 8; ++nt) {
            const int r0 = m0 + wm * 32 + mt * 16 + grp;
            const int c0 = n0 + wn * 64 + nt * 8 + 2 * qd;
            float v0 = acc[mt][nt][0], v1 = acc[mt][nt][1];
            float v2 = acc[mt][nt][2], v3 = acc[mt][nt][3];
            if (MODE == 0 || MODE == 3) {
                const float b0 = biasv[c0], b1 = biasv[c0 + 1];
                v0 += b0; v1 += b1; v2 += b0; v3 += b1;
            } else if (MODE == 1) {
                const float2 bm0 = *reinterpret_cast<const float2*>(
                    &bmp[(size_t)r0 * NN + c0]);
                const float2 bm1 = *reinterpret_cast<const float2*>(
                    &bmp[(size_t)(r0 + 8) * NN + c0]);
                // logits bounded (|S|*0.125 + bias ~ +-2): max-free softmax
                v0 = __expf(v0 * 0.125f + bm0.x);
                v1 = __expf(v1 * 0.125f + bm0.y);
                v2 = __expf(v2 * 0.125f + bm1.x);
                v3 = __expf(v3 * 0.125f + bm1.y);
            } else if (MODE == 2) {
                v0 *= inv[mt][0]; v1 *= inv[mt][0];
                v2 *= inv[mt][1]; v3 *= inv[mt][1];
            }
            *reinterpret_cast<float2*>(&Cp[(size_t)r0 * LDC + c0]) =
                make_float2(v0, v1);
            *reinterpret_cast<float2*>(&Cp[(size_t)(r0 + 8) * LDC + c0]) =
                make_float2(v2, v3);
        }
    }
}

// ---------------- launch ----------------
extern "C" void kernel_launch(void* const* d_in, const int* in_sizes, int n_in,
                              void* d_out, int out_size) {
    (void)in_sizes; (void)n_in; (void)out_size;
    const float* x      = (const float*)d_in[0];
    const float* gamma  = (const float*)d_in[1];
    const float* beta   = (const float*)d_in[2];
    const float* qkv_w  = (const float*)d_in[3];
    const float* qkv_b  = (const float*)d_in[4];
    const float* proj_w = (const float*)d_in[5];
    const float* proj_b = (const float*)d_in[6];
    const float* biases = (const float*)d_in[7];
    const int*   bidx   = (const int*)d_in[8];
    float* out = (float*)d_out;

    cudaFuncSetAttribute(mm_tf32<0>, cudaFuncAttributeMaxDynamicSharedMemorySize, MM_SMEM);
    cudaFuncSetAttribute(mm_tf32<1>, cudaFuncAttributeMaxDynamicSharedMemorySize, MM_SMEM);
    cudaFuncSetAttribute(mm_tf32<2>, cudaFuncAttributeMaxDynamicSharedMemorySize, MM_SMEM);
    cudaFuncSetAttribute(mm_tf32<3>, cudaFuncAttributeMaxDynamicSharedMemorySize, MM_SMEM);

    ln_kernel<<<BB * NN, 128>>>(x, gamma, beta);

    biasmat_kernel<<<dim3(NN * NN / 256, HH), 256>>>(biases, bidx);

    // QKV: [32768 x 512] @ [512 x 3072]
    mm_tf32<0><<<dim3(QKVV / 128, (BB * NN) / 128), 256, MM_SMEM>>>(qkv_w, nullptr, qkv_b);

    // P = exp(Q @ K^T * 0.125 + bias) per (b,h)  -> g_attn
    mm_tf32<1><<<dim3(NN / 128, NN / 128, BB * HH), 256, MM_SMEM>>>(nullptr, nullptr, nullptr);

    // (P @ V) / rowsum(P) per (b,h) -> g_av
    mm_tf32<2><<<dim3(DV / 128, NN / 128, BB * HH), 256, MM_SMEM>>>(nullptr, nullptr, nullptr);

    // proj: [32768 x 2048] @ [2048 x 512]
    mm_tf32<3><<<dim3(DIMV / 128, (BB * NN) / 128), 256, MM_SMEM>>>(proj_w, out, proj_b);
}

// round 14
// speedup vs baseline: 1.4699x; 1.4699x over previous
#include <cuda_runtime.h>
#include <cuda_fp16.h>
#include <cstdint>
#include <cstddef>

#define BB   32
#define NN   1024
#define DIMV 512
#define HH   8
#define KDV  64
#define DV   256
#define DHV  2048
#define QKVV 3072

// ---------------- scratch (device globals; allocation-free) ----------------
__device__ __half g_xn[(size_t)BB * NN * DIMV];        //  32 MB half
__device__ __half g_qkv[(size_t)BB * NN * QKVV];       // 192 MB half
__device__ float  g_attn[(size_t)BB * HH * NN * NN];   //   1 GB fp32 (logits/P)
__device__ __half g_av[(size_t)BB * NN * DHV];         // 128 MB half
__device__ float  g_biasmat[(size_t)HH * NN * NN];     //  32 MB fp32
__device__ __half g_wq[(size_t)QKVV * DIMV];           // qkv_w^T [3072][512]
__device__ __half g_wp[(size_t)DIMV * DHV];            // proj_w^T [512][2048]
__device__ __half g_vt[(size_t)BB * HH * DV * NN];     // V^T per bz [256][1024]

// ---------------- helpers ----------------
__device__ __forceinline__ uint32_t pack_h2(float lo, float hi) {
    __half2 h = __floats2half2_rn(lo, hi);
    return *reinterpret_cast<uint32_t*>(&h);
}

__device__ __forceinline__ void mma_f16(float c[4], const uint32_t a[4],
                                        const uint32_t b[2]) {
    asm volatile(
        "mma.sync.aligned.m16n8k16.row.col.f32.f16.f16.f32 "
        "{%0,%1,%2,%3}, {%4,%5,%6,%7}, {%8,%9}, {%0,%1,%2,%3};\n"
        : "+f"(c[0]), "+f"(c[1]), "+f"(c[2]), "+f"(c[3])
        : "r"(a[0]), "r"(a[1]), "r"(a[2]), "r"(a[3]), "r"(b[0]), "r"(b[1]));
}

__device__ __forceinline__ void cp16(void* smem_dst, const void* gsrc) {
    uint32_t d = (uint32_t)__cvta_generic_to_shared(smem_dst);
    asm volatile("cp.async.cg.shared.global [%0], [%1], 16;\n"
                 :: "r"(d), "l"(gsrc));
}
#define CP_COMMIT() asm volatile("cp.async.commit_group;\n" ::: "memory")
#define CP_WAIT1()  asm volatile("cp.async.wait_group 1;\n" ::: "memory")

// ---------------- LayerNorm -> half ----------------
__global__ void __launch_bounds__(128)
ln_kernel(const float* __restrict__ x, const float* __restrict__ gamma,
          const float* __restrict__ beta) {
    const int row = blockIdx.x;
    const int t = threadIdx.x;
    const float4 v = reinterpret_cast<const float4*>(x)[(size_t)row * (DIMV / 4) + t];
    float s  = v.x + v.y + v.z + v.w;
    float sq = v.x * v.x + v.y * v.y + v.z * v.z + v.w * v.w;
    #pragma unroll
    for (int o = 16; o > 0; o >>= 1) {
        s  += __shfl_xor_sync(0xffffffffu, s, o);
        sq += __shfl_xor_sync(0xffffffffu, sq, o);
    }
    __shared__ float ss[4], ssq[4];
    const int w = t >> 5, l = t & 31;
    if (l == 0) { ss[w] = s; ssq[w] = sq; }
    __syncthreads();
    if (t == 0) {
        float S  = ss[0] + ss[1] + ss[2] + ss[3];
        float SQ = ssq[0] + ssq[1] + ssq[2] + ssq[3];
        float mu = S * (1.0f / DIMV);
        float var = SQ * (1.0f / DIMV) - mu * mu;
        ss[0]  = mu;
        ssq[0] = rsqrtf(var + 1e-5f);
    }
    __syncthreads();
    const float mu = ss[0], rstd = ssq[0];
    const float4 g  = reinterpret_cast<const float4*>(gamma)[t];
    const float4 bt = reinterpret_cast<const float4*>(beta)[t];
    uint2 o;
    o.x = pack_h2((v.x - mu) * rstd * g.x + bt.x, (v.y - mu) * rstd * g.y + bt.y);
    o.y = pack_h2((v.z - mu) * rstd * g.z + bt.z, (v.w - mu) * rstd * g.w + bt.w);
    reinterpret_cast<uint2*>(g_xn)[(size_t)row * (DIMV / 4) + t] = o;
}

// ---------------- weight transpose f32[K][N] -> half[N][K] ----------------
__global__ void __launch_bounds__(256)
transpose_half(const float* __restrict__ src, __half* __restrict__ dst,
               int K, int N) {
    __shared__ float t[32][33];
    const int k0 = blockIdx.y * 32, n0 = blockIdx.x * 32;
    const int tx = threadIdx.x & 31, ty = threadIdx.x >> 5;
    #pragma unroll
    for (int i = 0; i < 32; i += 8)
        t[ty + i][tx] = src[(size_t)(k0 + ty + i) * N + n0 + tx];
    __syncthreads();
    #pragma unroll
    for (int i = 0; i < 32; i += 8)
        dst[(size_t)(n0 + ty + i) * K + k0 + tx] = __float2half_rn(t[tx][ty + i]);
}

// ---------------- V transpose: g_qkv half -> g_vt [bz][feat][token] --------
__global__ void __launch_bounds__(256)
vt_kernel() {
    __shared__ __half t[32][33];
    const int z = blockIdx.z;                 // bz
    const int b = z >> 3, h = z & 7;
    const int f0 = blockIdx.x * 32, tok0 = blockIdx.y * 32;
    const int tx = threadIdx.x & 31, ty = threadIdx.x >> 5;
    #pragma unroll
    for (int i = 0; i < 32; i += 8)
        t[ty + i][tx] = g_qkv[((size_t)(b * NN) + tok0 + ty + i) * QKVV
                              + h * 384 + 128 + f0 + tx];
    __syncthreads();
    #pragma unroll
    for (int i = 0; i < 32; i += 8)
        g_vt[((size_t)z * DV + f0 + ty + i) * NN + tok0 + tx] = t[tx][ty + i];
}

// ---------------- dense bias matrix ----------------
__global__ void __launch_bounds__(256)
biasmat_kernel(const float* __restrict__ biases, const int* __restrict__ bidx) {
    const int h = blockIdx.y;
    const size_t i = (size_t)blockIdx.x * 256 + threadIdx.x;
    g_biasmat[(size_t)h * NN * NN + i] = biases[h * 1024 + bidx[i]];
}

// ---------------- fp16 tensor-core GEMM, cp.async double buffer ------------
// BM=128, BN=128, BK=64 halfs; 256 threads = 8 warps (4M x 2N), warp 32x64.
// B always [N][K] half. A half except MODE 2 (fp32, cvt at fragment load).
// MODE 0: g_xn @ g_wq^T + qkv_b -> g_qkv (half)
// MODE 1: Q @ K^T (logits fp32) -> g_attn   (scale+bias in epilogue)
// MODE 2: P(fp32) @ Vt -> g_av (half)
// MODE 3: g_av @ g_wp^T + proj_b -> out (fp32)
#define MM_SMEM_H (2 * (128 * 72 * 2 + 128 * 72 * 2))          // 73728
#define MM_SMEM_F (2 * (128 * 68 * 4 + 128 * 72 * 2))          // 106496

template<int MODE>
__global__ void __launch_bounds__(256, 2)
mm_h(const __half* __restrict__ Bw, const void* __restrict__ Aarg,
     float* __restrict__ Cf, const float* __restrict__ biasv) {
    constexpr bool AFLOAT = (MODE == 2);
    constexpr int  LDA = (MODE == 0) ? DIMV : (MODE == 1) ? QKVV
                       : (MODE == 2) ? NN   : DHV;
    constexpr int  LDB = (MODE == 0) ? DIMV : (MODE == 1) ? QKVV
                       : (MODE == 2) ? NN   : DHV;
    constexpr int  LDC = (MODE == 0) ? QKVV : (MODE == 1) ? NN
                       : (MODE == 2) ? DHV  : DIMV;
    constexpr int  KDIM = (MODE == 0) ? DIMV : (MODE == 1) ? KDV
                        : (MODE == 2) ? NN   : DHV;
    constexpr int  NK = KDIM / 64;
    constexpr int  ABYTES = AFLOAT ? 128 * 68 * 4 : 128 * 72 * 2;
    constexpr int  STAGE  = ABYTES + 128 * 72 * 2;

    extern __shared__ char smc[];

    const int tid = threadIdx.x;
    const int m0 = blockIdx.y * 128;
    const int n0 = blockIdx.x * 128;

    const __half* Aph = nullptr;
    const float*  Apf = nullptr;
    const __half* Bp;
    __half* Cph = nullptr;
    const float* bmp = nullptr;
    if (MODE == 0) {
        Aph = g_xn; Bp = Bw; Cph = g_qkv;
    } else if (MODE == 1) {
        const int bz = blockIdx.z, b = bz >> 3, h = bz & 7;
        Aph = g_qkv + (size_t)b * NN * QKVV + h * 384;          // Q
        Bp  = g_qkv + (size_t)b * NN * QKVV + h * 384 + 64;     // K rows
        Cf  = g_attn + (size_t)bz * NN * NN;
        bmp = g_biasmat + (size_t)h * NN * NN;
    } else if (MODE == 2) {
        const int bz = blockIdx.z, b = bz >> 3, h = bz & 7;
        Apf = g_attn + (size_t)bz * NN * NN;
        Bp  = g_vt + (size_t)bz * DV * NN;
        Cph = g_av + (size_t)b * NN * DHV + h * DV;
    } else {
        Aph = (const __half*)Aarg; Bp = Bw;
    }

    const int wid = tid >> 5, lane = tid & 31;
    const int wm = wid >> 1, wn = wid & 1;
    const int grp = lane >> 2, qd = lane & 3;

    const int crow = tid >> 1;                // copy row 0..127

    auto issue_tile = [&](int kt) {
        char* As = smc + (kt & 1) * STAGE;
        char* Bs = As + ABYTES;
        const int k0 = kt * 64;
        if (AFLOAT) {
            #pragma unroll
            for (int i = 0; i < 8; ++i) {
                const int c = (tid & 1) * 8 + i;
                cp16(As + crow * 272 + c * 16,
                     Apf + (size_t)(m0 + crow) * LDA + k0 + c * 4);
            }
        } else {
            #pragma unroll
            for (int i = 0; i < 4; ++i) {
                const int c = (tid & 1) * 4 + i;
                cp16(As + crow * 144 + c * 16,
                     Aph + (size_t)(m0 + crow) * LDA + k0 + c * 8);
            }
        }
        #pragma unroll
        for (int i = 0; i < 4; ++i) {
            const int c = (tid & 1) * 4 + i;
            cp16(Bs + crow * 144 + c * 16,
                 Bp + (size_t)(n0 + crow) * LDB + k0 + c * 8);
        }
    };

    float acc[2][8][4] = {};

    issue_tile(0); CP_COMMIT();
    if (NK > 1) issue_tile(1);
    CP_COMMIT();

    for (int kt = 0; kt < NK; ++kt) {
        CP_WAIT1();
        __syncthreads();
        const char* As = smc + (kt & 1) * STAGE;
        const char* Bs = As + ABYTES;
        const __half* Ash = (const __half*)As;
        const float*  Asf = (const float*)As;
        const __half* Bsh = (const __half*)Bs;
        #pragma unroll
        for (int ks = 0; ks < 4; ++ks) {
            const int kc = ks * 16 + 2 * qd;
            uint32_t af[2][4];
            #pragma unroll
            for (int mt = 0; mt < 2; ++mt) {
                const int mr = wm * 32 + mt * 16 + grp;
                if (AFLOAT) {
                    const float2 t0 = *reinterpret_cast<const float2*>(&Asf[mr * 68 + kc]);
                    const float2 t1 = *reinterpret_cast<const float2*>(&Asf[(mr + 8) * 68 + kc]);
                    const float2 t2 = *reinterpret_cast<const float2*>(&Asf[mr * 68 + kc + 8]);
                    const float2 t3 = *reinterpret_cast<const float2*>(&Asf[(mr + 8) * 68 + kc + 8]);
                    af[mt][0] = pack_h2(t0.x, t0.y);
                    af[mt][1] = pack_h2(t1.x, t1.y);
                    af[mt][2] = pack_h2(t2.x, t2.y);
                    af[mt][3] = pack_h2(t3.x, t3.y);
                } else {
                    af[mt][0] = *reinterpret_cast<const uint32_t*>(&Ash[mr * 72 + kc]);
                    af[mt][1] = *reinterpret_cast<const uint32_t*>(&Ash[(mr + 8) * 72 + kc]);
                    af[mt][2] = *reinterpret_cast<const uint32_t*>(&Ash[mr * 72 + kc + 8]);
                    af[mt][3] = *reinterpret_cast<const uint32_t*>(&Ash[(mr + 8) * 72 + kc + 8]);
                }
            }
            uint32_t bf[8][2];
            #pragma unroll
            for (int nt = 0; nt < 8; ++nt) {
                const int nc = wn * 64 + nt * 8 + grp;
                bf[nt][0] = *reinterpret_cast<const uint32_t*>(&Bsh[nc * 72 + kc]);
                bf[nt][1] = *reinterpret_cast<const uint32_t*>(&Bsh[nc * 72 + kc + 8]);
            }
            #pragma unroll
            for (int mt = 0; mt < 2; ++mt)
                #pragma unroll
                for (int nt = 0; nt < 8; ++nt)
                    mma_f16(acc[mt][nt], af[mt], bf[nt]);
        }
        __syncthreads();
        if (kt + 2 < NK) issue_tile(kt + 2);
        CP_COMMIT();
    }

    // --- epilogue ---
    #pragma unroll
    for (int mt = 0; mt < 2; ++mt) {
        #pragma unroll
        for (int nt = 0; nt < 8; ++nt) {
            const int r0 = m0 + wm * 32 + mt * 16 + grp;
            const int c0 = n0 + wn * 64 + nt * 8 + 2 * qd;
            float v0 = acc[mt][nt][0], v1 = acc[mt][nt][1];
            float v2 = acc[mt][nt][2], v3 = acc[mt][nt][3];
            if (MODE == 0) {
                const float b0 = biasv[c0], b1 = biasv[c0 + 1];
                *reinterpret_cast<uint32_t*>(&Cph[(size_t)r0 * LDC + c0]) =
                    pack_h2(v0 + b0, v1 + b1);
                *reinterpret_cast<uint32_t*>(&Cph[(size_t)(r0 + 8) * LDC + c0]) =
                    pack_h2(v2 + b0, v3 + b1);
            } else if (MODE == 1) {
                const float2 bm0 = *reinterpret_cast<const float2*>(
                    &bmp[(size_t)r0 * NN + c0]);
                const float2 bm1 = *reinterpret_cast<const float2*>(
                    &bmp[(size_t)(r0 + 8) * NN + c0]);
                *reinterpret_cast<float2*>(&Cf[(size_t)r0 * LDC + c0]) =
                    make_float2(v0 * 0.125f + bm0.x, v1 * 0.125f + bm0.y);
                *reinterpret_cast<float2*>(&Cf[(size_t)(r0 + 8) * LDC + c0]) =
                    make_float2(v2 * 0.125f + bm1.x, v3 * 0.125f + bm1.y);
            } else if (MODE == 2) {
                *reinterpret_cast<uint32_t*>(&Cph[(size_t)r0 * LDC + c0]) =
                    pack_h2(v0, v1);
                *reinterpret_cast<uint32_t*>(&Cph[(size_t)(r0 + 8) * LDC + c0]) =
                    pack_h2(v2, v3);
            } else {
                const float b0 = biasv[c0], b1 = biasv[c0 + 1];
                *reinterpret_cast<float2*>(&Cf[(size_t)r0 * LDC + c0]) =
                    make_float2(v0 + b0, v1 + b1);
                *reinterpret_cast<float2*>(&Cf[(size_t)(r0 + 8) * LDC + c0]) =
                    make_float2(v2 + b0, v3 + b1);
            }
        }
    }
}

// ---------------- softmax over k (in-place on g_attn, fp32) ----------------
__global__ void __launch_bounds__(256)
softmax_kernel() {
    const size_t base = (size_t)blockIdx.x * NN;
    float4* p = reinterpret_cast<float4*>(g_attn + base);
    const int t = threadIdx.x;
    const int w = t >> 5, l = t & 31;
    __shared__ float red[8];
    float4 v = p[t];
    float m = fmaxf(fmaxf(v.x, v.y), fmaxf(v.z, v.w));
    #pragma unroll
    for (int o = 16; o > 0; o >>= 1) m = fmaxf(m, __shfl_xor_sync(0xffffffffu, m, o));
    if (l == 0) red[w] = m;
    __syncthreads();
    if (t == 0) {
        float mm = red[0];
        #pragma unroll
        for (int i = 1; i < 8; ++i) mm = fmaxf(mm, red[i]);
        red[0] = mm;
    }
    __syncthreads();
    m = red[0];
    float4 e;
    e.x = __expf(v.x - m); e.y = __expf(v.y - m);
    e.z = __expf(v.z - m); e.w = __expf(v.w - m);
    float s = e.x + e.y + e.z + e.w;
    #pragma unroll
    for (int o = 16; o > 0; o >>= 1) s += __shfl_xor_sync(0xffffffffu, s, o);
    __syncthreads();
    if (l == 0) red[w] = s;
    __syncthreads();
    if (t == 0) {
        float tot = 0.f;
        #pragma unroll
        for (int i = 0; i < 8; ++i) tot += red[i];
        red[0] = tot;
    }
    __syncthreads();
    const float inv = 1.0f / red[0];
    e.x *= inv; e.y *= inv; e.z *= inv; e.w *= inv;
    p[t] = e;
}

// ---------------- launch ----------------
extern "C" void kernel_launch(void* const* d_in, const int* in_sizes, int n_in,
                              void* d_out, int out_size) {
    (void)in_sizes; (void)n_in; (void)out_size;
    const float* x      = (const float*)d_in[0];
    const float* gamma  = (const float*)d_in[1];
    const float* beta   = (const float*)d_in[2];
    const float* qkv_w  = (const float*)d_in[3];
    const float* qkv_b  = (const float*)d_in[4];
    const float* proj_w = (const float*)d_in[5];
    const float* proj_b = (const float*)d_in[6];
    const float* biases = (const float*)d_in[7];
    const int*   bidx   = (const int*)d_in[8];
    float* out = (float*)d_out;

    cudaFuncSetAttribute(mm_h<0>, cudaFuncAttributeMaxDynamicSharedMemorySize, MM_SMEM_H);
    cudaFuncSetAttribute(mm_h<1>, cudaFuncAttributeMaxDynamicSharedMemorySize, MM_SMEM_H);
    cudaFuncSetAttribute(mm_h<2>, cudaFuncAttributeMaxDynamicSharedMemorySize, MM_SMEM_F);
    cudaFuncSetAttribute(mm_h<3>, cudaFuncAttributeMaxDynamicSharedMemorySize, MM_SMEM_H);

    __half *wq_p = nullptr, *wp_p = nullptr, *xn_p = nullptr, *av_p = nullptr;
    cudaGetSymbolAddress((void**)&wq_p, g_wq);
    cudaGetSymbolAddress((void**)&wp_p, g_wp);
    cudaGetSymbolAddress((void**)&xn_p, g_xn);
    cudaGetSymbolAddress((void**)&av_p, g_av);

    ln_kernel<<<BB * NN, 128>>>(x, gamma, beta);

    transpose_half<<<dim3(QKVV / 32, DIMV / 32), 256>>>(qkv_w, wq_p, DIMV, QKVV);
    transpose_half<<<dim3(DIMV / 32, DHV / 32), 256>>>(proj_w, wp_p, DHV, DIMV);

    biasmat_kernel<<<dim3(NN * NN / 256, HH), 256>>>(biases, bidx);

    // QKV: [32768 x 512] @ [512 x 3072] -> half
    mm_h<0><<<dim3(QKVV / 128, (BB * NN) / 128), 256, MM_SMEM_H>>>(wq_p, nullptr, nullptr, qkv_b);

    // V transpose for mm2
    vt_kernel<<<dim3(DV / 32, NN / 32, BB * HH), 256>>>();

    // logits per (b,h) -> g_attn fp32
    mm_h<1><<<dim3(NN / 128, NN / 128, BB * HH), 256, MM_SMEM_H>>>(nullptr, nullptr, nullptr, nullptr);

    softmax_kernel<<<BB * HH * NN, 256>>>();

    // P @ Vt per (b,h) -> g_av half
    mm_h<2><<<dim3(DV / 128, NN / 128, BB * HH), 256, MM_SMEM_F>>>(nullptr, nullptr, nullptr, nullptr);

    // proj: [32768 x 2048] @ [2048 x 512] -> out fp32
    mm_h<3><<<dim3(DIMV / 128, (BB * NN) / 128), 256, MM_SMEM_H>>>(wp_p, av_p, out, proj_b);
}

// round 15
// speedup vs baseline: 1.7826x; 1.2127x over previous
#include <cuda_runtime.h>
#include <cuda_fp16.h>
#include <cstdint>
#include <cstddef>

#define BB   32
#define NN   1024
#define DIMV 512
#define HH   8
#define KDV  64
#define DV   256
#define DHV  2048
#define QKVV 3072

// ---------------- scratch (device globals; allocation-free) ----------------
__device__ __half g_xn[(size_t)BB * NN * DIMV];        //  32 MB half
__device__ __half g_qkv[(size_t)BB * NN * QKVV];       // 192 MB half
__device__ __half g_attn[(size_t)BB * HH * NN * NN];   // 512 MB half (logits/P)
__device__ __half g_av[(size_t)BB * NN * DHV];         // 128 MB half
__device__ float  g_biasmat[(size_t)HH * NN * NN];     //  32 MB fp32
__device__ __half g_wq[(size_t)QKVV * DIMV];           // qkv_w^T [3072][512]
__device__ __half g_wp[(size_t)DIMV * DHV];            // proj_w^T [512][2048]
__device__ __half g_vt[(size_t)BB * HH * DV * NN];     // V^T per bz [256][1024]

// ---------------- helpers ----------------
__device__ __forceinline__ uint32_t pack_h2(float lo, float hi) {
    __half2 h = __floats2half2_rn(lo, hi);
    return *reinterpret_cast<uint32_t*>(&h);
}

__device__ __forceinline__ void mma_f16(float c[4], const uint32_t a[4],
                                        const uint32_t b[2]) {
    asm volatile(
        "mma.sync.aligned.m16n8k16.row.col.f32.f16.f16.f32 "
        "{%0,%1,%2,%3}, {%4,%5,%6,%7}, {%8,%9}, {%0,%1,%2,%3};\n"
        : "+f"(c[0]), "+f"(c[1]), "+f"(c[2]), "+f"(c[3])
        : "r"(a[0]), "r"(a[1]), "r"(a[2]), "r"(a[3]), "r"(b[0]), "r"(b[1]));
}

__device__ __forceinline__ void cp16(void* smem_dst, const void* gsrc) {
    uint32_t d = (uint32_t)__cvta_generic_to_shared(smem_dst);
    asm volatile("cp.async.cg.shared.global [%0], [%1], 16;\n"
                 :: "r"(d), "l"(gsrc));
}
#define CP_COMMIT() asm volatile("cp.async.commit_group;\n" ::: "memory")
#define CP_WAIT1()  asm volatile("cp.async.wait_group 1;\n" ::: "memory")

// ---------------- LayerNorm -> half ----------------
__global__ void __launch_bounds__(128)
ln_kernel(const float* __restrict__ x, const float* __restrict__ gamma,
          const float* __restrict__ beta) {
    const int row = blockIdx.x;
    const int t = threadIdx.x;
    const float4 v = reinterpret_cast<const float4*>(x)[(size_t)row * (DIMV / 4) + t];
    float s  = v.x + v.y + v.z + v.w;
    float sq = v.x * v.x + v.y * v.y + v.z * v.z + v.w * v.w;
    #pragma unroll
    for (int o = 16; o > 0; o >>= 1) {
        s  += __shfl_xor_sync(0xffffffffu, s, o);
        sq += __shfl_xor_sync(0xffffffffu, sq, o);
    }
    __shared__ float ss[4], ssq[4];
    const int w = t >> 5, l = t & 31;
    if (l == 0) { ss[w] = s; ssq[w] = sq; }
    __syncthreads();
    if (t == 0) {
        float S  = ss[0] + ss[1] + ss[2] + ss[3];
        float SQ = ssq[0] + ssq[1] + ssq[2] + ssq[3];
        float mu = S * (1.0f / DIMV);
        float var = SQ * (1.0f / DIMV) - mu * mu;
        ss[0]  = mu;
        ssq[0] = rsqrtf(var + 1e-5f);
    }
    __syncthreads();
    const float mu = ss[0], rstd = ssq[0];
    const float4 g  = reinterpret_cast<const float4*>(gamma)[t];
    const float4 bt = reinterpret_cast<const float4*>(beta)[t];
    uint2 o;
    o.x = pack_h2((v.x - mu) * rstd * g.x + bt.x, (v.y - mu) * rstd * g.y + bt.y);
    o.y = pack_h2((v.z - mu) * rstd * g.z + bt.z, (v.w - mu) * rstd * g.w + bt.w);
    reinterpret_cast<uint2*>(g_xn)[(size_t)row * (DIMV / 4) + t] = o;
}

// ---------------- weight transpose f32[K][N] -> half[N][K] ----------------
__global__ void __launch_bounds__(256)
transpose_half(const float* __restrict__ src, __half* __restrict__ dst,
               int K, int N) {
    __shared__ float t[32][33];
    const int k0 = blockIdx.y * 32, n0 = blockIdx.x * 32;
    const int tx = threadIdx.x & 31, ty = threadIdx.x >> 5;
    #pragma unroll
    for (int i = 0; i < 32; i += 8)
        t[ty + i][tx] = src[(size_t)(k0 + ty + i) * N + n0 + tx];
    __syncthreads();
    #pragma unroll
    for (int i = 0; i < 32; i += 8)
        dst[(size_t)(n0 + ty + i) * K + k0 + tx] = __float2half_rn(t[tx][ty + i]);
}

// ---------------- V transpose: g_qkv half -> g_vt [bz][feat][token] --------
__global__ void __launch_bounds__(256)
vt_kernel() {
    __shared__ __half t[32][33];
    const int z = blockIdx.z;
    const int b = z >> 3, h = z & 7;
    const int f0 = blockIdx.x * 32, tok0 = blockIdx.y * 32;
    const int tx = threadIdx.x & 31, ty = threadIdx.x >> 5;
    #pragma unroll
    for (int i = 0; i < 32; i += 8)
        t[ty + i][tx] = g_qkv[((size_t)(b * NN) + tok0 + ty + i) * QKVV
                              + h * 384 + 128 + f0 + tx];
    __syncthreads();
    #pragma unroll
    for (int i = 0; i < 32; i += 8)
        g_vt[((size_t)z * DV + f0 + ty + i) * NN + tok0 + tx] = t[tx][ty + i];
}

// ---------------- dense bias matrix ----------------
__global__ void __launch_bounds__(256)
biasmat_kernel(const float* __restrict__ biases, const int* __restrict__ bidx) {
    const int h = blockIdx.y;
    const size_t i = (size_t)blockIdx.x * 256 + threadIdx.x;
    g_biasmat[(size_t)h * NN * NN + i] = biases[h * 1024 + bidx[i]];
}

// ---------------- fp16 tensor-core GEMM, cp.async double buffer ------------
// BM=128, BN=128, BK=64 halfs; 256 threads = 8 warps (4M x 2N), warp 32x64.
// All operands half ([M][K] row-major A; [N][K] B). Accum fp32.
// MODE 0: g_xn @ g_wq^T + qkv_b -> g_qkv (half)
// MODE 1: Q @ K^T * 0.125 + bias -> g_attn (half logits)
// MODE 2: P(half) @ Vt -> g_av (half)
// MODE 3: g_av @ g_wp^T + proj_b -> out (fp32)
#define MM_SMEM_H (2 * (128 * 72 * 2 + 128 * 72 * 2))          // 73728

template<int MODE>
__global__ void __launch_bounds__(256, 2)
mm_h(const __half* __restrict__ Bw, const void* __restrict__ Aarg,
     float* __restrict__ Cf, const float* __restrict__ biasv) {
    constexpr int  LDA = (MODE == 0) ? DIMV : (MODE == 1) ? QKVV
                       : (MODE == 2) ? NN   : DHV;
    constexpr int  LDB = (MODE == 0) ? DIMV : (MODE == 1) ? QKVV
                       : (MODE == 2) ? NN   : DHV;
    constexpr int  LDC = (MODE == 0) ? QKVV : (MODE == 1) ? NN
                       : (MODE == 2) ? DHV  : DIMV;
    constexpr int  KDIM = (MODE == 0) ? DIMV : (MODE == 1) ? KDV
                        : (MODE == 2) ? NN   : DHV;
    constexpr int  NK = KDIM / 64;
    constexpr int  ABYTES = 128 * 72 * 2;
    constexpr int  STAGE  = ABYTES + 128 * 72 * 2;

    extern __shared__ char smc[];

    const int tid = threadIdx.x;
    const int m0 = blockIdx.y * 128;
    const int n0 = blockIdx.x * 128;

    const __half* Aph = nullptr;
    const __half* Bp;
    __half* Cph = nullptr;
    const float* bmp = nullptr;
    if (MODE == 0) {
        Aph = g_xn; Bp = Bw; Cph = g_qkv;
    } else if (MODE == 1) {
        const int bz = blockIdx.z, b = bz >> 3, h = bz & 7;
        Aph = g_qkv + (size_t)b * NN * QKVV + h * 384;          // Q
        Bp  = g_qkv + (size_t)b * NN * QKVV + h * 384 + 64;     // K rows
        Cph = g_attn + (size_t)bz * NN * NN;
        bmp = g_biasmat + (size_t)h * NN * NN;
    } else if (MODE == 2) {
        const int bz = blockIdx.z, b = bz >> 3, h = bz & 7;
        Aph = g_attn + (size_t)bz * NN * NN;                    // P (half)
        Bp  = g_vt + (size_t)bz * DV * NN;
        Cph = g_av + (size_t)b * NN * DHV + h * DV;
    } else {
        Aph = (const __half*)Aarg; Bp = Bw;
    }

    const int wid = tid >> 5, lane = tid & 31;
    const int wm = wid >> 1, wn = wid & 1;
    const int grp = lane >> 2, qd = lane & 3;

    const int crow = tid >> 1;

    auto issue_tile = [&](int kt) {
        char* As = smc + (kt & 1) * STAGE;
        char* Bs = As + ABYTES;
        const int k0 = kt * 64;
        #pragma unroll
        for (int i = 0; i < 4; ++i) {
            const int c = (tid & 1) * 4 + i;
            cp16(As + crow * 144 + c * 16,
                 Aph + (size_t)(m0 + crow) * LDA + k0 + c * 8);
        }
        #pragma unroll
        for (int i = 0; i < 4; ++i) {
            const int c = (tid & 1) * 4 + i;
            cp16(Bs + crow * 144 + c * 16,
                 Bp + (size_t)(n0 + crow) * LDB + k0 + c * 8);
        }
    };

    float acc[2][8][4] = {};

    issue_tile(0); CP_COMMIT();
    if (NK > 1) issue_tile(1);
    CP_COMMIT();

    for (int kt = 0; kt < NK; ++kt) {
        CP_WAIT1();
        __syncthreads();
        const char* As = smc + (kt & 1) * STAGE;
        const char* Bs = As + ABYTES;
        const __half* Ash = (const __half*)As;
        const __half* Bsh = (const __half*)Bs;
        #pragma unroll
        for (int ks = 0; ks < 4; ++ks) {
            const int kc = ks * 16 + 2 * qd;
            uint32_t af[2][4];
            #pragma unroll
            for (int mt = 0; mt < 2; ++mt) {
                const int mr = wm * 32 + mt * 16 + grp;
                af[mt][0] = *reinterpret_cast<const uint32_t*>(&Ash[mr * 72 + kc]);
                af[mt][1] = *reinterpret_cast<const uint32_t*>(&Ash[(mr + 8) * 72 + kc]);
                af[mt][2] = *reinterpret_cast<const uint32_t*>(&Ash[mr * 72 + kc + 8]);
                af[mt][3] = *reinterpret_cast<const uint32_t*>(&Ash[(mr + 8) * 72 + kc + 8]);
            }
            uint32_t bf[8][2];
            #pragma unroll
            for (int nt = 0; nt < 8; ++nt) {
                const int nc = wn * 64 + nt * 8 + grp;
                bf[nt][0] = *reinterpret_cast<const uint32_t*>(&Bsh[nc * 72 + kc]);
                bf[nt][1] = *reinterpret_cast<const uint32_t*>(&Bsh[nc * 72 + kc + 8]);
            }
            #pragma unroll
            for (int mt = 0; mt < 2; ++mt)
                #pragma unroll
                for (int nt = 0; nt < 8; ++nt)
                    mma_f16(acc[mt][nt], af[mt], bf[nt]);
        }
        __syncthreads();
        if (kt + 2 < NK) issue_tile(kt + 2);
        CP_COMMIT();
    }

    // --- epilogue ---
    #pragma unroll
    for (int mt = 0; mt < 2; ++mt) {
        #pragma unroll
        for (int nt = 0; nt < 8; ++nt) {
            const int r0 = m0 + wm * 32 + mt * 16 + grp;
            const int c0 = n0 + wn * 64 + nt * 8 + 2 * qd;
            float v0 = acc[mt][nt][0], v1 = acc[mt][nt][1];
            float v2 = acc[mt][nt][2], v3 = acc[mt][nt][3];
            if (MODE == 0) {
                const float b0 = biasv[c0], b1 = biasv[c0 + 1];
                *reinterpret_cast<uint32_t*>(&Cph[(size_t)r0 * LDC + c0]) =
                    pack_h2(v0 + b0, v1 + b1);
                *reinterpret_cast<uint32_t*>(&Cph[(size_t)(r0 + 8) * LDC + c0]) =
                    pack_h2(v2 + b0, v3 + b1);
            } else if (MODE == 1) {
                const float2 bm0 = *reinterpret_cast<const float2*>(
                    &bmp[(size_t)r0 * NN + c0]);
                const float2 bm1 = *reinterpret_cast<const float2*>(
                    &bmp[(size_t)(r0 + 8) * NN + c0]);
                *reinterpret_cast<uint32_t*>(&Cph[(size_t)r0 * LDC + c0]) =
                    pack_h2(v0 * 0.125f + bm0.x, v1 * 0.125f + bm0.y);
                *reinterpret_cast<uint32_t*>(&Cph[(size_t)(r0 + 8) * LDC + c0]) =
                    pack_h2(v2 * 0.125f + bm1.x, v3 * 0.125f + bm1.y);
            } else if (MODE == 2) {
                *reinterpret_cast<uint32_t*>(&Cph[(size_t)r0 * LDC + c0]) =
                    pack_h2(v0, v1);
                *reinterpret_cast<uint32_t*>(&Cph[(size_t)(r0 + 8) * LDC + c0]) =
                    pack_h2(v2, v3);
            } else {
                const float b0 = biasv[c0], b1 = biasv[c0 + 1];
                *reinterpret_cast<float2*>(&Cf[(size_t)r0 * LDC + c0]) =
                    make_float2(v0 + b0, v1 + b1);
                *reinterpret_cast<float2*>(&Cf[(size_t)(r0 + 8) * LDC + c0]) =
                    make_float2(v2 + b0, v3 + b1);
            }
        }
    }
}

// ---------------- softmax over k (in-place on half g_attn) ----------------
// 256 threads/row; each thread owns 4 halfs (2 x half2). fp32 math inside.
__global__ void __launch_bounds__(256)
softmax_kernel() {
    const size_t base = (size_t)blockIdx.x * NN;
    uint2* p = reinterpret_cast<uint2*>(g_attn + base);
    const int t = threadIdx.x;
    const int w = t >> 5, l = t & 31;
    __shared__ float red[8];
    const uint2 raw = p[t];
    const __half2 h0 = *reinterpret_cast<const __half2*>(&raw.x);
    const __half2 h1 = *reinterpret_cast<const __half2*>(&raw.y);
    const float2 f0 = __half22float2(h0);
    const float2 f1 = __half22float2(h1);
    float m = fmaxf(fmaxf(f0.x, f0.y), fmaxf(f1.x, f1.y));
    #pragma unroll
    for (int o = 16; o > 0; o >>= 1) m = fmaxf(m, __shfl_xor_sync(0xffffffffu, m, o));
    if (l == 0) red[w] = m;
    __syncthreads();
    if (t == 0) {
        float mm = red[0];
        #pragma unroll
        for (int i = 1; i < 8; ++i) mm = fmaxf(mm, red[i]);
        red[0] = mm;
    }
    __syncthreads();
    m = red[0];
    float e0 = __expf(f0.x - m), e1 = __expf(f0.y - m);
    float e2 = __expf(f1.x - m), e3 = __expf(f1.y - m);
    float s = e0 + e1 + e2 + e3;
    #pragma unroll
    for (int o = 16; o > 0; o >>= 1) s += __shfl_xor_sync(0xffffffffu, s, o);
    __syncthreads();
    if (l == 0) red[w] = s;
    __syncthreads();
    if (t == 0) {
        float tot = 0.f;
        #pragma unroll
        for (int i = 0; i < 8; ++i) tot += red[i];
        red[0] = tot;
    }
    __syncthreads();
    const float inv = 1.0f / red[0];
    uint2 o;
    o.x = pack_h2(e0 * inv, e1 * inv);
    o.y = pack_h2(e2 * inv, e3 * inv);
    p[t] = o;
}

// ---------------- launch ----------------
extern "C" void kernel_launch(void* const* d_in, const int* in_sizes, int n_in,
                              void* d_out, int out_size) {
    (void)in_sizes; (void)n_in; (void)out_size;
    const float* x      = (const float*)d_in[0];
    const float* gamma  = (const float*)d_in[1];
    const float* beta   = (const float*)d_in[2];
    const float* qkv_w  = (const float*)d_in[3];
    const float* qkv_b  = (const float*)d_in[4];
    const float* proj_w = (const float*)d_in[5];
    const float* proj_b = (const float*)d_in[6];
    const float* biases = (const float*)d_in[7];
    const int*   bidx   = (const int*)d_in[8];
    float* out = (float*)d_out;

    cudaFuncSetAttribute(mm_h<0>, cudaFuncAttributeMaxDynamicSharedMemorySize, MM_SMEM_H);
    cudaFuncSetAttribute(mm_h<1>, cudaFuncAttributeMaxDynamicSharedMemorySize, MM_SMEM_H);
    cudaFuncSetAttribute(mm_h<2>, cudaFuncAttributeMaxDynamicSharedMemorySize, MM_SMEM_H);
    cudaFuncSetAttribute(mm_h<3>, cudaFuncAttributeMaxDynamicSharedMemorySize, MM_SMEM_H);

    __half *wq_p = nullptr, *wp_p = nullptr, *av_p = nullptr;
    cudaGetSymbolAddress((void**)&wq_p, g_wq);
    cudaGetSymbolAddress((void**)&wp_p, g_wp);
    cudaGetSymbolAddress((void**)&av_p, g_av);

    ln_kernel<<<BB * NN, 128>>>(x, gamma, beta);

    transpose_half<<<dim3(QKVV / 32, DIMV / 32), 256>>>(qkv_w, wq_p, DIMV, QKVV);
    transpose_half<<<dim3(DIMV / 32, DHV / 32), 256>>>(proj_w, wp_p, DHV, DIMV);

    biasmat_kernel<<<dim3(NN * NN / 256, HH), 256>>>(biases, bidx);

    // QKV: [32768 x 512] @ [512 x 3072] -> half
    mm_h<0><<<dim3(QKVV / 128, (BB * NN) / 128), 256, MM_SMEM_H>>>(wq_p, nullptr, nullptr, qkv_b);

    // V transpose for mm2
    vt_kernel<<<dim3(DV / 32, NN / 32, BB * HH), 256>>>();

    // logits per (b,h) -> g_attn (half)
    mm_h<1><<<dim3(NN / 128, NN / 128, BB * HH), 256, MM_SMEM_H>>>(nullptr, nullptr, nullptr, nullptr);

    softmax_kernel<<<BB * HH * NN, 256>>>();

    // P @ Vt per (b,h) -> g_av half
    mm_h<2><<<dim3(DV / 128, NN / 128, BB * HH), 256, MM_SMEM_H>>>(nullptr, nullptr, nullptr, nullptr);

    // proj: [32768 x 2048] @ [2048 x 512] -> out fp32
    mm_h<3><<<dim3(DIMV / 128, (BB * NN) / 128), 256, MM_SMEM_H>>>(wp_p, av_p, out, proj_b);
}

// round 16
// speedup vs baseline: 1.8233x; 1.0229x over previous
#include <cuda_runtime.h>
#include <cuda_fp16.h>
#include <cstdint>
#include <cstddef>

#define BB   32
#define NN   1024
#define DIMV 512
#define HH   8
#define KDV  64
#define DV   256
#define DHV  2048
#define QKVV 3072

// ---------------- scratch (device globals; allocation-free) ----------------
__device__ __half g_xn[(size_t)BB * NN * DIMV];        //  32 MB half
__device__ __half g_qkv[(size_t)BB * NN * QKVV];       // 192 MB half
__device__ __half g_attn[(size_t)BB * HH * NN * NN];   // 512 MB half (logits/P)
__device__ __half g_av[(size_t)BB * NN * DHV];         // 128 MB half
__device__ __half g_biasmat[(size_t)HH * NN * NN];     //  16 MB half
__device__ __half g_wq[(size_t)QKVV * DIMV];           // qkv_w^T [3072][512]
__device__ __half g_wp[(size_t)DIMV * DHV];            // proj_w^T [512][2048]
__device__ __half g_vt[(size_t)BB * HH * DV * NN];     // V^T per bz [256][1024]

// ---------------- helpers ----------------
__device__ __forceinline__ uint32_t pack_h2(float lo, float hi) {
    __half2 h = __floats2half2_rn(lo, hi);
    return *reinterpret_cast<uint32_t*>(&h);
}

__device__ __forceinline__ void mma_f16(float c[4], const uint32_t a[4],
                                        const uint32_t b[2]) {
    asm volatile(
        "mma.sync.aligned.m16n8k16.row.col.f32.f16.f16.f32 "
        "{%0,%1,%2,%3}, {%4,%5,%6,%7}, {%8,%9}, {%0,%1,%2,%3};\n"
        : "+f"(c[0]), "+f"(c[1]), "+f"(c[2]), "+f"(c[3])
        : "r"(a[0]), "r"(a[1]), "r"(a[2]), "r"(a[3]), "r"(b[0]), "r"(b[1]));
}

__device__ __forceinline__ void cp16(void* smem_dst, const void* gsrc) {
    uint32_t d = (uint32_t)__cvta_generic_to_shared(smem_dst);
    asm volatile("cp.async.cg.shared.global [%0], [%1], 16;\n"
                 :: "r"(d), "l"(gsrc));
}
#define CP_COMMIT() asm volatile("cp.async.commit_group;\n" ::: "memory")
#define CP_WAIT1()  asm volatile("cp.async.wait_group 1;\n" ::: "memory")

// ---------------- LayerNorm -> half ----------------
__global__ void __launch_bounds__(128)
ln_kernel(const float* __restrict__ x, const float* __restrict__ gamma,
          const float* __restrict__ beta) {
    const int row = blockIdx.x;
    const int t = threadIdx.x;
    const float4 v = reinterpret_cast<const float4*>(x)[(size_t)row * (DIMV / 4) + t];
    float s  = v.x + v.y + v.z + v.w;
    float sq = v.x * v.x + v.y * v.y + v.z * v.z + v.w * v.w;
    #pragma unroll
    for (int o = 16; o > 0; o >>= 1) {
        s  += __shfl_xor_sync(0xffffffffu, s, o);
        sq += __shfl_xor_sync(0xffffffffu, sq, o);
    }
    __shared__ float ss[4], ssq[4];
    const int w = t >> 5, l = t & 31;
    if (l == 0) { ss[w] = s; ssq[w] = sq; }
    __syncthreads();
    if (t == 0) {
        float S  = ss[0] + ss[1] + ss[2] + ss[3];
        float SQ = ssq[0] + ssq[1] + ssq[2] + ssq[3];
        float mu = S * (1.0f / DIMV);
        float var = SQ * (1.0f / DIMV) - mu * mu;
        ss[0]  = mu;
        ssq[0] = rsqrtf(var + 1e-5f);
    }
    __syncthreads();
    const float mu = ss[0], rstd = ssq[0];
    const float4 g  = reinterpret_cast<const float4*>(gamma)[t];
    const float4 bt = reinterpret_cast<const float4*>(beta)[t];
    uint2 o;
    o.x = pack_h2((v.x - mu) * rstd * g.x + bt.x, (v.y - mu) * rstd * g.y + bt.y);
    o.y = pack_h2((v.z - mu) * rstd * g.z + bt.z, (v.w - mu) * rstd * g.w + bt.w);
    reinterpret_cast<uint2*>(g_xn)[(size_t)row * (DIMV / 4) + t] = o;
}

// ---------------- weight transpose f32[K][N] -> half[N][K] ----------------
__global__ void __launch_bounds__(256)
transpose_half(const float* __restrict__ src, __half* __restrict__ dst,
               int K, int N) {
    __shared__ float t[32][33];
    const int k0 = blockIdx.y * 32, n0 = blockIdx.x * 32;
    const int tx = threadIdx.x & 31, ty = threadIdx.x >> 5;
    #pragma unroll
    for (int i = 0; i < 32; i += 8)
        t[ty + i][tx] = src[(size_t)(k0 + ty + i) * N + n0 + tx];
    __syncthreads();
    #pragma unroll
    for (int i = 0; i < 32; i += 8)
        dst[(size_t)(n0 + ty + i) * K + k0 + tx] = __float2half_rn(t[tx][ty + i]);
}

// ---------------- V transpose (vectorized): g_qkv -> g_vt [bz][feat][tok] --
// 64 tok x 64 feat tile; half2 global loads and stores on both sides.
__global__ void __launch_bounds__(256)
vt_kernel() {
    __shared__ __half t[64][65];
    const int z = blockIdx.z;
    const int b = z >> 3, h = z & 7;
    const int f0 = blockIdx.x * 64, tok0 = blockIdx.y * 64;
    const int tid = threadIdx.x;
    #pragma unroll
    for (int i = 0; i < 8; ++i) {
        const int idx = tid + i * 256;        // 0..2047 = 64 tok x 32 h2
        const int tok = idx >> 5, f2 = idx & 31;
        const uint32_t v = *reinterpret_cast<const uint32_t*>(
            &g_qkv[((size_t)(b * NN) + tok0 + tok) * QKVV + h * 384 + 128 + f0 + f2 * 2]);
        const __half2 hv = *reinterpret_cast<const __half2*>(&v);
        t[tok][f2 * 2]     = __low2half(hv);
        t[tok][f2 * 2 + 1] = __high2half(hv);
    }
    __syncthreads();
    #pragma unroll
    for (int i = 0; i < 8; ++i) {
        const int idx = tid + i * 256;        // 64 feat x 32 tok-pairs
        const int feat = idx >> 5, t2 = idx & 31;
        __half2 hv = __halves2half2(t[t2 * 2][feat], t[t2 * 2 + 1][feat]);
        *reinterpret_cast<uint32_t*>(
            &g_vt[((size_t)z * DV + f0 + feat) * NN + tok0 + t2 * 2]) =
            *reinterpret_cast<uint32_t*>(&hv);
    }
}

// ---------------- dense bias matrix (half) ----------------
__global__ void __launch_bounds__(256)
biasmat_kernel(const float* __restrict__ biases, const int* __restrict__ bidx) {
    const int h = blockIdx.y;
    const size_t i = (size_t)blockIdx.x * 256 + threadIdx.x;
    g_biasmat[(size_t)h * NN * NN + i] = __float2half_rn(biases[h * 1024 + bidx[i]]);
}

// ---------------- fp16 tensor-core GEMM, cp.async double buffer ------------
// BM=128, BN=128, BK=64 halfs; 256 threads = 8 warps (4M x 2N), warp 32x64.
// MODE 0: g_xn @ g_wq^T + qkv_b -> g_qkv (half)
// MODE 1: Q @ K^T * 0.125 + bias(half) -> g_attn (half logits)
// MODE 2: P(half) @ Vt -> g_av (half)
// MODE 3: g_av @ g_wp^T + proj_b -> out (fp32)
#define MM_SMEM_H (2 * (128 * 72 * 2 + 128 * 72 * 2))          // 73728

template<int MODE>
__global__ void __launch_bounds__(256, 2)
mm_h(const __half* __restrict__ Bw, const void* __restrict__ Aarg,
     float* __restrict__ Cf, const float* __restrict__ biasv) {
    constexpr int  LDA = (MODE == 0) ? DIMV : (MODE == 1) ? QKVV
                       : (MODE == 2) ? NN   : DHV;
    constexpr int  LDB = (MODE == 0) ? DIMV : (MODE == 1) ? QKVV
                       : (MODE == 2) ? NN   : DHV;
    constexpr int  LDC = (MODE == 0) ? QKVV : (MODE == 1) ? NN
                       : (MODE == 2) ? DHV  : DIMV;
    constexpr int  KDIM = (MODE == 0) ? DIMV : (MODE == 1) ? KDV
                        : (MODE == 2) ? NN   : DHV;
    constexpr int  NK = KDIM / 64;
    constexpr int  ABYTES = 128 * 72 * 2;
    constexpr int  STAGE  = ABYTES + 128 * 72 * 2;

    extern __shared__ char smc[];

    const int tid = threadIdx.x;
    const int m0 = blockIdx.y * 128;
    const int n0 = blockIdx.x * 128;

    const __half* Aph = nullptr;
    const __half* Bp;
    __half* Cph = nullptr;
    const __half* bmp = nullptr;
    if (MODE == 0) {
        Aph = g_xn; Bp = Bw; Cph = g_qkv;
    } else if (MODE == 1) {
        const int bz = blockIdx.z, b = bz >> 3, h = bz & 7;
        Aph = g_qkv + (size_t)b * NN * QKVV + h * 384;          // Q
        Bp  = g_qkv + (size_t)b * NN * QKVV + h * 384 + 64;     // K rows
        Cph = g_attn + (size_t)bz * NN * NN;
        bmp = g_biasmat + (size_t)h * NN * NN;
    } else if (MODE == 2) {
        const int bz = blockIdx.z, b = bz >> 3, h = bz & 7;
        Aph = g_attn + (size_t)bz * NN * NN;                    // P (half)
        Bp  = g_vt + (size_t)bz * DV * NN;
        Cph = g_av + (size_t)b * NN * DHV + h * DV;
    } else {
        Aph = (const __half*)Aarg; Bp = Bw;
    }

    const int wid = tid >> 5, lane = tid & 31;
    const int wm = wid >> 1, wn = wid & 1;
    const int grp = lane >> 2, qd = lane & 3;

    const int crow = tid >> 1;

    auto issue_tile = [&](int kt) {
        char* As = smc + (kt & 1) * STAGE;
        char* Bs = As + ABYTES;
        const int k0 = kt * 64;
        #pragma unroll
        for (int i = 0; i < 4; ++i) {
            const int c = (tid & 1) * 4 + i;
            cp16(As + crow * 144 + c * 16,
                 Aph + (size_t)(m0 + crow) * LDA + k0 + c * 8);
        }
        #pragma unroll
        for (int i = 0; i < 4; ++i) {
            const int c = (tid & 1) * 4 + i;
            cp16(Bs + crow * 144 + c * 16,
                 Bp + (size_t)(n0 + crow) * LDB + k0 + c * 8);
        }
    };

    float acc[2][8][4] = {};

    issue_tile(0); CP_COMMIT();
    if (NK > 1) issue_tile(1);
    CP_COMMIT();

    for (int kt = 0; kt < NK; ++kt) {
        CP_WAIT1();
        __syncthreads();
        const char* As = smc + (kt & 1) * STAGE;
        const char* Bs = As + ABYTES;
        const __half* Ash = (const __half*)As;
        const __half* Bsh = (const __half*)Bs;
        #pragma unroll
        for (int ks = 0; ks < 4; ++ks) {
            const int kc = ks * 16 + 2 * qd;
            uint32_t af[2][4];
            #pragma unroll
            for (int mt = 0; mt < 2; ++mt) {
                const int mr = wm * 32 + mt * 16 + grp;
                af[mt][0] = *reinterpret_cast<const uint32_t*>(&Ash[mr * 72 + kc]);
                af[mt][1] = *reinterpret_cast<const uint32_t*>(&Ash[(mr + 8) * 72 + kc]);
                af[mt][2] = *reinterpret_cast<const uint32_t*>(&Ash[mr * 72 + kc + 8]);
                af[mt][3] = *reinterpret_cast<const uint32_t*>(&Ash[(mr + 8) * 72 + kc + 8]);
            }
            uint32_t bf[8][2];
            #pragma unroll
            for (int nt = 0; nt < 8; ++nt) {
                const int nc = wn * 64 + nt * 8 + grp;
                bf[nt][0] = *reinterpret_cast<const uint32_t*>(&Bsh[nc * 72 + kc]);
                bf[nt][1] = *reinterpret_cast<const uint32_t*>(&Bsh[nc * 72 + kc + 8]);
            }
            #pragma unroll
            for (int mt = 0; mt < 2; ++mt)
                #pragma unroll
                for (int nt = 0; nt < 8; ++nt)
                    mma_f16(acc[mt][nt], af[mt], bf[nt]);
        }
        __syncthreads();
        if (kt + 2 < NK) issue_tile(kt + 2);
        CP_COMMIT();
    }

    // --- epilogue ---
    #pragma unroll
    for (int mt = 0; mt < 2; ++mt) {
        #pragma unroll
        for (int nt = 0; nt < 8; ++nt) {
            const int r0 = m0 + wm * 32 + mt * 16 + grp;
            const int c0 = n0 + wn * 64 + nt * 8 + 2 * qd;
            float v0 = acc[mt][nt][0], v1 = acc[mt][nt][1];
            float v2 = acc[mt][nt][2], v3 = acc[mt][nt][3];
            if (MODE == 0) {
                const float b0 = biasv[c0], b1 = biasv[c0 + 1];
                *reinterpret_cast<uint32_t*>(&Cph[(size_t)r0 * LDC + c0]) =
                    pack_h2(v0 + b0, v1 + b1);
                *reinterpret_cast<uint32_t*>(&Cph[(size_t)(r0 + 8) * LDC + c0]) =
                    pack_h2(v2 + b0, v3 + b1);
            } else if (MODE == 1) {
                const __half2 bh0 = *reinterpret_cast<const __half2*>(
                    &bmp[(size_t)r0 * NN + c0]);
                const __half2 bh1 = *reinterpret_cast<const __half2*>(
                    &bmp[(size_t)(r0 + 8) * NN + c0]);
                const float2 bm0 = __half22float2(bh0);
                const float2 bm1 = __half22float2(bh1);
                *reinterpret_cast<uint32_t*>(&Cph[(size_t)r0 * LDC + c0]) =
                    pack_h2(v0 * 0.125f + bm0.x, v1 * 0.125f + bm0.y);
                *reinterpret_cast<uint32_t*>(&Cph[(size_t)(r0 + 8) * LDC + c0]) =
                    pack_h2(v2 * 0.125f + bm1.x, v3 * 0.125f + bm1.y);
            } else if (MODE == 2) {
                *reinterpret_cast<uint32_t*>(&Cph[(size_t)r0 * LDC + c0]) =
                    pack_h2(v0, v1);
                *reinterpret_cast<uint32_t*>(&Cph[(size_t)(r0 + 8) * LDC + c0]) =
                    pack_h2(v2, v3);
            } else {
                const float b0 = biasv[c0], b1 = biasv[c0 + 1];
                *reinterpret_cast<float2*>(&Cf[(size_t)r0 * LDC + c0]) =
                    make_float2(v0 + b0, v1 + b1);
                *reinterpret_cast<float2*>(&Cf[(size_t)(r0 + 8) * LDC + c0]) =
                    make_float2(v2 + b0, v3 + b1);
            }
        }
    }
}

// ---------------- softmax over k (in-place on half g_attn) ----------------
__global__ void __launch_bounds__(256)
softmax_kernel() {
    const size_t base = (size_t)blockIdx.x * NN;
    uint2* p = reinterpret_cast<uint2*>(g_attn + base);
    const int t = threadIdx.x;
    const int w = t >> 5, l = t & 31;
    __shared__ float red[8];
    const uint2 raw = p[t];
    const __half2 h0 = *reinterpret_cast<const __half2*>(&raw.x);
    const __half2 h1 = *reinterpret_cast<const __half2*>(&raw.y);
    const float2 f0 = __half22float2(h0);
    const float2 f1 = __half22float2(h1);
    float m = fmaxf(fmaxf(f0.x, f0.y), fmaxf(f1.x, f1.y));
    #pragma unroll
    for (int o = 16; o > 0; o >>= 1) m = fmaxf(m, __shfl_xor_sync(0xffffffffu, m, o));
    if (l == 0) red[w] = m;
    __syncthreads();
    if (t == 0) {
        float mm = red[0];
        #pragma unroll
        for (int i = 1; i < 8; ++i) mm = fmaxf(mm, red[i]);
        red[0] = mm;
    }
    __syncthreads();
    m = red[0];
    float e0 = __expf(f0.x - m), e1 = __expf(f0.y - m);
    float e2 = __expf(f1.x - m), e3 = __expf(f1.y - m);
    float s = e0 + e1 + e2 + e3;
    #pragma unroll
    for (int o = 16; o > 0; o >>= 1) s += __shfl_xor_sync(0xffffffffu, s, o);
    __syncthreads();
    if (l == 0) red[w] = s;
    __syncthreads();
    if (t == 0) {
        float tot = 0.f;
        #pragma unroll
        for (int i = 0; i < 8; ++i) tot += red[i];
        red[0] = tot;
    }
    __syncthreads();
    const float inv = 1.0f / red[0];
    uint2 o;
    o.x = pack_h2(e0 * inv, e1 * inv);
    o.y = pack_h2(e2 * inv, e3 * inv);
    p[t] = o;
}

// ---------------- launch ----------------
extern "C" void kernel_launch(void* const* d_in, const int* in_sizes, int n_in,
                              void* d_out, int out_size) {
    (void)in_sizes; (void)n_in; (void)out_size;
    const float* x      = (const float*)d_in[0];
    const float* gamma  = (const float*)d_in[1];
    const float* beta   = (const float*)d_in[2];
    const float* qkv_w  = (const float*)d_in[3];
    const float* qkv_b  = (const float*)d_in[4];
    const float* proj_w = (const float*)d_in[5];
    const float* proj_b = (const float*)d_in[6];
    const float* biases = (const float*)d_in[7];
    const int*   bidx   = (const int*)d_in[8];
    float* out = (float*)d_out;

    cudaFuncSetAttribute(mm_h<0>, cudaFuncAttributeMaxDynamicSharedMemorySize, MM_SMEM_H);
    cudaFuncSetAttribute(mm_h<1>, cudaFuncAttributeMaxDynamicSharedMemorySize, MM_SMEM_H);
    cudaFuncSetAttribute(mm_h<2>, cudaFuncAttributeMaxDynamicSharedMemorySize, MM_SMEM_H);
    cudaFuncSetAttribute(mm_h<3>, cudaFuncAttributeMaxDynamicSharedMemorySize, MM_SMEM_H);

    __half *wq_p = nullptr, *wp_p = nullptr, *av_p = nullptr;
    cudaGetSymbolAddress((void**)&wq_p, g_wq);
    cudaGetSymbolAddress((void**)&wp_p, g_wp);
    cudaGetSymbolAddress((void**)&av_p, g_av);

    ln_kernel<<<BB * NN, 128>>>(x, gamma, beta);

    transpose_half<<<dim3(QKVV / 32, DIMV / 32), 256>>>(qkv_w, wq_p, DIMV, QKVV);
    transpose_half<<<dim3(DIMV / 32, DHV / 32), 256>>>(proj_w, wp_p, DHV, DIMV);

    biasmat_kernel<<<dim3(NN * NN / 256, HH), 256>>>(biases, bidx);

    // QKV: [32768 x 512] @ [512 x 3072] -> half
    mm_h<0><<<dim3(QKVV / 128, (BB * NN) / 128), 256, MM_SMEM_H>>>(wq_p, nullptr, nullptr, qkv_b);

    // V transpose for mm2 (vectorized)
    vt_kernel<<<dim3(DV / 64, NN / 64, BB * HH), 256>>>();

    // logits per (b,h) -> g_attn (half)
    mm_h<1><<<dim3(NN / 128, NN / 128, BB * HH), 256, MM_SMEM_H>>>(nullptr, nullptr, nullptr, nullptr);

    softmax_kernel<<<BB * HH * NN, 256>>>();

    // P @ Vt per (b,h) -> g_av half
    mm_h<2><<<dim3(DV / 128, NN / 128, BB * HH), 256, MM_SMEM_H>>>(nullptr, nullptr, nullptr, nullptr);

    // proj: [32768 x 2048] @ [2048 x 512] -> out fp32
    mm_h<3><<<dim3(DIMV / 128, (BB * NN) / 128), 256, MM_SMEM_H>>>(wp_p, av_p, out, proj_b);
}

// round 17
// speedup vs baseline: 1.8551x; 1.0175x over previous
#include <cuda_runtime.h>
#include <cuda_fp16.h>
#include <cstdint>
#include <cstddef>

#define BB   32
#define NN   1024
#define DIMV 512
#define HH   8
#define KDV  64
#define DV   256
#define DHV  2048
#define QKVV 3072

// ---------------- scratch (device globals; allocation-free) ----------------
__device__ __half g_xn[(size_t)BB * NN * DIMV];        //  32 MB half
__device__ __half g_qkv[(size_t)BB * NN * QKVV];       // 192 MB half
__device__ __half g_attn[(size_t)BB * HH * NN * NN];   // 512 MB half (logits/P)
__device__ __half g_av[(size_t)BB * NN * DHV];         // 128 MB half
__device__ __half g_biasmat[(size_t)HH * NN * NN];     //  16 MB half
__device__ __half g_wq[(size_t)QKVV * DIMV];           // qkv_w^T [3072][512]
__device__ __half g_wp[(size_t)DIMV * DHV];            // proj_w^T [512][2048]
__device__ __half g_vt[(size_t)BB * HH * DV * NN];     // V^T per bz [256][1024]

// ---------------- helpers ----------------
__device__ __forceinline__ uint32_t pack_h2(float lo, float hi) {
    __half2 h = __floats2half2_rn(lo, hi);
    return *reinterpret_cast<uint32_t*>(&h);
}

__device__ __forceinline__ void mma_f16(float c[4], const uint32_t a[4],
                                        const uint32_t b[2]) {
    asm volatile(
        "mma.sync.aligned.m16n8k16.row.col.f32.f16.f16.f32 "
        "{%0,%1,%2,%3}, {%4,%5,%6,%7}, {%8,%9}, {%0,%1,%2,%3};\n"
        : "+f"(c[0]), "+f"(c[1]), "+f"(c[2]), "+f"(c[3])
        : "r"(a[0]), "r"(a[1]), "r"(a[2]), "r"(a[3]), "r"(b[0]), "r"(b[1]));
}

__device__ __forceinline__ void cp16(void* smem_dst, const void* gsrc) {
    uint32_t d = (uint32_t)__cvta_generic_to_shared(smem_dst);
    asm volatile("cp.async.cg.shared.global [%0], [%1], 16;\n"
                 :: "r"(d), "l"(gsrc));
}
#define CP_COMMIT() asm volatile("cp.async.commit_group;\n" ::: "memory")
#define CP_WAIT1()  asm volatile("cp.async.wait_group 1;\n" ::: "memory")

// ---------------- LayerNorm -> half ----------------
__global__ void __launch_bounds__(128)
ln_kernel(const float* __restrict__ x, const float* __restrict__ gamma,
          const float* __restrict__ beta) {
    const int row = blockIdx.x;
    const int t = threadIdx.x;
    const float4 v = reinterpret_cast<const float4*>(x)[(size_t)row * (DIMV / 4) + t];
    float s  = v.x + v.y + v.z + v.w;
    float sq = v.x * v.x + v.y * v.y + v.z * v.z + v.w * v.w;
    #pragma unroll
    for (int o = 16; o > 0; o >>= 1) {
        s  += __shfl_xor_sync(0xffffffffu, s, o);
        sq += __shfl_xor_sync(0xffffffffu, sq, o);
    }
    __shared__ float ss[4], ssq[4];
    const int w = t >> 5, l = t & 31;
    if (l == 0) { ss[w] = s; ssq[w] = sq; }
    __syncthreads();
    if (t == 0) {
        float S  = ss[0] + ss[1] + ss[2] + ss[3];
        float SQ = ssq[0] + ssq[1] + ssq[2] + ssq[3];
        float mu = S * (1.0f / DIMV);
        float var = SQ * (1.0f / DIMV) - mu * mu;
        ss[0]  = mu;
        ssq[0] = rsqrtf(var + 1e-5f);
    }
    __syncthreads();
    const float mu = ss[0], rstd = ssq[0];
    const float4 g  = reinterpret_cast<const float4*>(gamma)[t];
    const float4 bt = reinterpret_cast<const float4*>(beta)[t];
    uint2 o;
    o.x = pack_h2((v.x - mu) * rstd * g.x + bt.x, (v.y - mu) * rstd * g.y + bt.y);
    o.y = pack_h2((v.z - mu) * rstd * g.z + bt.z, (v.w - mu) * rstd * g.w + bt.w);
    reinterpret_cast<uint2*>(g_xn)[(size_t)row * (DIMV / 4) + t] = o;
}

// ---------------- weight transpose f32[K][N] -> half[N][K] ----------------
__global__ void __launch_bounds__(256)
transpose_half(const float* __restrict__ src, __half* __restrict__ dst,
               int K, int N) {
    __shared__ float t[32][33];
    const int k0 = blockIdx.y * 32, n0 = blockIdx.x * 32;
    const int tx = threadIdx.x & 31, ty = threadIdx.x >> 5;
    #pragma unroll
    for (int i = 0; i < 32; i += 8)
        t[ty + i][tx] = src[(size_t)(k0 + ty + i) * N + n0 + tx];
    __syncthreads();
    #pragma unroll
    for (int i = 0; i < 32; i += 8)
        dst[(size_t)(n0 + ty + i) * K + k0 + tx] = __float2half_rn(t[tx][ty + i]);
}

// ---------------- V transpose (vectorized): g_qkv -> g_vt [bz][feat][tok] --
__global__ void __launch_bounds__(256)
vt_kernel() {
    __shared__ __half t[64][65];
    const int z = blockIdx.z;
    const int b = z >> 3, h = z & 7;
    const int f0 = blockIdx.x * 64, tok0 = blockIdx.y * 64;
    const int tid = threadIdx.x;
    #pragma unroll
    for (int i = 0; i < 8; ++i) {
        const int idx = tid + i * 256;
        const int tok = idx >> 5, f2 = idx & 31;
        const uint32_t v = *reinterpret_cast<const uint32_t*>(
            &g_qkv[((size_t)(b * NN) + tok0 + tok) * QKVV + h * 384 + 128 + f0 + f2 * 2]);
        const __half2 hv = *reinterpret_cast<const __half2*>(&v);
        t[tok][f2 * 2]     = __low2half(hv);
        t[tok][f2 * 2 + 1] = __high2half(hv);
    }
    __syncthreads();
    #pragma unroll
    for (int i = 0; i < 8; ++i) {
        const int idx = tid + i * 256;
        const int feat = idx >> 5, t2 = idx & 31;
        __half2 hv = __halves2half2(t[t2 * 2][feat], t[t2 * 2 + 1][feat]);
        *reinterpret_cast<uint32_t*>(
            &g_vt[((size_t)z * DV + f0 + feat) * NN + tok0 + t2 * 2]) =
            *reinterpret_cast<uint32_t*>(&hv);
    }
}

// ---------------- dense bias matrix (half) ----------------
__global__ void __launch_bounds__(256)
biasmat_kernel(const float* __restrict__ biases, const int* __restrict__ bidx) {
    const int h = blockIdx.y;
    const size_t i = (size_t)blockIdx.x * 256 + threadIdx.x;
    g_biasmat[(size_t)h * NN * NN + i] = __float2half_rn(biases[h * 1024 + bidx[i]]);
}

// ---------------- fp16 tensor-core GEMM (modes 0,2,3) ----------------
#define MM_SMEM_H (2 * (128 * 72 * 2 + 128 * 72 * 2))          // 73728

template<int MODE>
__global__ void __launch_bounds__(256, 2)
mm_h(const __half* __restrict__ Bw, const void* __restrict__ Aarg,
     float* __restrict__ Cf, const float* __restrict__ biasv) {
    constexpr int  LDA = (MODE == 0) ? DIMV : (MODE == 2) ? NN : DHV;
    constexpr int  LDB = LDA;
    constexpr int  LDC = (MODE == 0) ? QKVV : (MODE == 2) ? DHV : DIMV;
    constexpr int  KDIM = LDA;
    constexpr int  NK = KDIM / 64;
    constexpr int  ABYTES = 128 * 72 * 2;
    constexpr int  STAGE  = ABYTES + 128 * 72 * 2;

    extern __shared__ char smc[];

    const int tid = threadIdx.x;
    const int m0 = blockIdx.y * 128;
    const int n0 = blockIdx.x * 128;

    const __half* Aph = nullptr;
    const __half* Bp;
    __half* Cph = nullptr;
    if (MODE == 0) {
        Aph = g_xn; Bp = Bw; Cph = g_qkv;
    } else if (MODE == 2) {
        const int bz = blockIdx.z, b = bz >> 3, h = bz & 7;
        Aph = g_attn + (size_t)bz * NN * NN;
        Bp  = g_vt + (size_t)bz * DV * NN;
        Cph = g_av + (size_t)b * NN * DHV + h * DV;
    } else {
        Aph = (const __half*)Aarg; Bp = Bw;
    }

    const int wid = tid >> 5, lane = tid & 31;
    const int wm = wid >> 1, wn = wid & 1;
    const int grp = lane >> 2, qd = lane & 3;
    const int crow = tid >> 1;

    auto issue_tile = [&](int kt) {
        char* As = smc + (kt & 1) * STAGE;
        char* Bs = As + ABYTES;
        const int k0 = kt * 64;
        #pragma unroll
        for (int i = 0; i < 4; ++i) {
            const int c = (tid & 1) * 4 + i;
            cp16(As + crow * 144 + c * 16,
                 Aph + (size_t)(m0 + crow) * LDA + k0 + c * 8);
        }
        #pragma unroll
        for (int i = 0; i < 4; ++i) {
            const int c = (tid & 1) * 4 + i;
            cp16(Bs + crow * 144 + c * 16,
                 Bp + (size_t)(n0 + crow) * LDB + k0 + c * 8);
        }
    };

    float acc[2][8][4] = {};

    issue_tile(0); CP_COMMIT();
    if (NK > 1) issue_tile(1);
    CP_COMMIT();

    for (int kt = 0; kt < NK; ++kt) {
        CP_WAIT1();
        __syncthreads();
        const char* As = smc + (kt & 1) * STAGE;
        const char* Bs = As + ABYTES;
        const __half* Ash = (const __half*)As;
        const __half* Bsh = (const __half*)Bs;
        #pragma unroll
        for (int ks = 0; ks < 4; ++ks) {
            const int kc = ks * 16 + 2 * qd;
            uint32_t af[2][4];
            #pragma unroll
            for (int mt = 0; mt < 2; ++mt) {
                const int mr = wm * 32 + mt * 16 + grp;
                af[mt][0] = *reinterpret_cast<const uint32_t*>(&Ash[mr * 72 + kc]);
                af[mt][1] = *reinterpret_cast<const uint32_t*>(&Ash[(mr + 8) * 72 + kc]);
                af[mt][2] = *reinterpret_cast<const uint32_t*>(&Ash[mr * 72 + kc + 8]);
                af[mt][3] = *reinterpret_cast<const uint32_t*>(&Ash[(mr + 8) * 72 + kc + 8]);
            }
            uint32_t bf[8][2];
            #pragma unroll
            for (int nt = 0; nt < 8; ++nt) {
                const int nc = wn * 64 + nt * 8 + grp;
                bf[nt][0] = *reinterpret_cast<const uint32_t*>(&Bsh[nc * 72 + kc]);
                bf[nt][1] = *reinterpret_cast<const uint32_t*>(&Bsh[nc * 72 + kc + 8]);
            }
            #pragma unroll
            for (int mt = 0; mt < 2; ++mt)
                #pragma unroll
                for (int nt = 0; nt < 8; ++nt)
                    mma_f16(acc[mt][nt], af[mt], bf[nt]);
        }
        __syncthreads();
        if (kt + 2 < NK) issue_tile(kt + 2);
        CP_COMMIT();
    }

    #pragma unroll
    for (int mt = 0; mt < 2; ++mt) {
        #pragma unroll
        for (int nt = 0; nt < 8; ++nt) {
            const int r0 = m0 + wm * 32 + mt * 16 + grp;
            const int c0 = n0 + wn * 64 + nt * 8 + 2 * qd;
            float v0 = acc[mt][nt][0], v1 = acc[mt][nt][1];
            float v2 = acc[mt][nt][2], v3 = acc[mt][nt][3];
            if (MODE == 0) {
                const float b0 = biasv[c0], b1 = biasv[c0 + 1];
                *reinterpret_cast<uint32_t*>(&Cph[(size_t)r0 * LDC + c0]) =
                    pack_h2(v0 + b0, v1 + b1);
                *reinterpret_cast<uint32_t*>(&Cph[(size_t)(r0 + 8) * LDC + c0]) =
                    pack_h2(v2 + b0, v3 + b1);
            } else if (MODE == 2) {
                *reinterpret_cast<uint32_t*>(&Cph[(size_t)r0 * LDC + c0]) =
                    pack_h2(v0, v1);
                *reinterpret_cast<uint32_t*>(&Cph[(size_t)(r0 + 8) * LDC + c0]) =
                    pack_h2(v2, v3);
            } else {
                const float b0 = biasv[c0], b1 = biasv[c0 + 1];
                *reinterpret_cast<float2*>(&Cf[(size_t)r0 * LDC + c0]) =
                    make_float2(v0 + b0, v1 + b1);
                *reinterpret_cast<float2*>(&Cf[(size_t)(r0 + 8) * LDC + c0]) =
                    make_float2(v2 + b0, v3 + b1);
            }
        }
    }
}

// ---------------- widened QK kernel: 128 x 512 logits strip per CTA --------
// Q tile loaded once (16 KB); 4 K subtiles double-buffered; per-subtile
// epilogue = *0.125 + bias(half) -> g_attn half.
// smem: Q[128][72] + 2 x K[128][72] halfs = 55296 B -> 2 CTAs/SM.
#define W1_Q_BYTES (128 * 72 * 2)
#define W1_K_BYTES (128 * 72 * 2)
#define W1_SMEM (W1_Q_BYTES + 2 * W1_K_BYTES)

__global__ void __launch_bounds__(256, 2)
qk_wide() {
    extern __shared__ char smc[];
    __half* Qs = (__half*)smc;

    const int bz = blockIdx.z, b = bz >> 3, h = bz & 7;
    const int m0 = blockIdx.y * 128;
    const int n0 = blockIdx.x * 512;
    const int tid = threadIdx.x;
    const int wid = tid >> 5, lane = tid & 31;
    const int wm = wid >> 1, wn = wid & 1;
    const int grp = lane >> 2, qd = lane & 3;
    const int crow = tid >> 1;

    const __half* Qp = g_qkv + (size_t)b * NN * QKVV + h * 384;
    const __half* Kp = Qp + 64;
    __half* Cph = g_attn + (size_t)bz * NN * NN;
    const __half* bmp = g_biasmat + (size_t)h * NN * NN;

    auto issue_k = [&](int st) {
        char* Ks = smc + W1_Q_BYTES + (st & 1) * W1_K_BYTES;
        #pragma unroll
        for (int i = 0; i < 4; ++i) {
            const int c = (tid & 1) * 4 + i;
            cp16(Ks + crow * 144 + c * 16,
                 Kp + (size_t)(n0 + st * 128 + crow) * QKVV + c * 8);
        }
    };

    // group 0: Q + K subtile 0 ; group 1: K subtile 1
    {
        #pragma unroll
        for (int i = 0; i < 4; ++i) {
            const int c = (tid & 1) * 4 + i;
            cp16(smc + crow * 144 + c * 16,
                 Qp + (size_t)(m0 + crow) * QKVV + c * 8);
        }
        issue_k(0); CP_COMMIT();
        issue_k(1); CP_COMMIT();
    }

    #pragma unroll
    for (int st = 0; st < 4; ++st) {
        CP_WAIT1();
        __syncthreads();
        const __half* Ksh = (const __half*)(smc + W1_Q_BYTES + (st & 1) * W1_K_BYTES);

        float acc[2][8][4] = {};
        #pragma unroll
        for (int ks = 0; ks < 4; ++ks) {
            const int kc = ks * 16 + 2 * qd;
            uint32_t af[2][4];
            #pragma unroll
            for (int mt = 0; mt < 2; ++mt) {
                const int mr = wm * 32 + mt * 16 + grp;
                af[mt][0] = *reinterpret_cast<const uint32_t*>(&Qs[mr * 72 + kc]);
                af[mt][1] = *reinterpret_cast<const uint32_t*>(&Qs[(mr + 8) * 72 + kc]);
                af[mt][2] = *reinterpret_cast<const uint32_t*>(&Qs[mr * 72 + kc + 8]);
                af[mt][3] = *reinterpret_cast<const uint32_t*>(&Qs[(mr + 8) * 72 + kc + 8]);
            }
            uint32_t bf[8][2];
            #pragma unroll
            for (int nt = 0; nt < 8; ++nt) {
                const int nc = wn * 64 + nt * 8 + grp;
                bf[nt][0] = *reinterpret_cast<const uint32_t*>(&Ksh[nc * 72 + kc]);
                bf[nt][1] = *reinterpret_cast<const uint32_t*>(&Ksh[nc * 72 + kc + 8]);
            }
            #pragma unroll
            for (int mt = 0; mt < 2; ++mt)
                #pragma unroll
                for (int nt = 0; nt < 8; ++nt)
                    mma_f16(acc[mt][nt], af[mt], bf[nt]);
        }
        __syncthreads();
        if (st + 2 < 4) issue_k(st + 2);
        CP_COMMIT();

        // epilogue for this subtile
        const int nbase = n0 + st * 128;
        #pragma unroll
        for (int mt = 0; mt < 2; ++mt) {
            #pragma unroll
            for (int nt = 0; nt < 8; ++nt) {
                const int r0 = m0 + wm * 32 + mt * 16 + grp;
                const int c0 = nbase + wn * 64 + nt * 8 + 2 * qd;
                const __half2 bh0 = *reinterpret_cast<const __half2*>(
                    &bmp[(size_t)r0 * NN + c0]);
                const __half2 bh1 = *reinterpret_cast<const __half2*>(
                    &bmp[(size_t)(r0 + 8) * NN + c0]);
                const float2 bm0 = __half22float2(bh0);
                const float2 bm1 = __half22float2(bh1);
                *reinterpret_cast<uint32_t*>(&Cph[(size_t)r0 * NN + c0]) =
                    pack_h2(acc[mt][nt][0] * 0.125f + bm0.x,
                            acc[mt][nt][1] * 0.125f + bm0.y);
                *reinterpret_cast<uint32_t*>(&Cph[(size_t)(r0 + 8) * NN + c0]) =
                    pack_h2(acc[mt][nt][2] * 0.125f + bm1.x,
                            acc[mt][nt][3] * 0.125f + bm1.y);
            }
        }
    }
}

// ---------------- softmax over k (in-place on half g_attn) ----------------
__global__ void __launch_bounds__(256)
softmax_kernel() {
    const size_t base = (size_t)blockIdx.x * NN;
    uint2* p = reinterpret_cast<uint2*>(g_attn + base);
    const int t = threadIdx.x;
    const int w = t >> 5, l = t & 31;
    __shared__ float red[8];
    const uint2 raw = p[t];
    const __half2 h0 = *reinterpret_cast<const __half2*>(&raw.x);
    const __half2 h1 = *reinterpret_cast<const __half2*>(&raw.y);
    const float2 f0 = __half22float2(h0);
    const float2 f1 = __half22float2(h1);
    float m = fmaxf(fmaxf(f0.x, f0.y), fmaxf(f1.x, f1.y));
    #pragma unroll
    for (int o = 16; o > 0; o >>= 1) m = fmaxf(m, __shfl_xor_sync(0xffffffffu, m, o));
    if (l == 0) red[w] = m;
    __syncthreads();
    if (t == 0) {
        float mm = red[0];
        #pragma unroll
        for (int i = 1; i < 8; ++i) mm = fmaxf(mm, red[i]);
        red[0] = mm;
    }
    __syncthreads();
    m = red[0];
    float e0 = __expf(f0.x - m), e1 = __expf(f0.y - m);
    float e2 = __expf(f1.x - m), e3 = __expf(f1.y - m);
    float s = e0 + e1 + e2 + e3;
    #pragma unroll
    for (int o = 16; o > 0; o >>= 1) s += __shfl_xor_sync(0xffffffffu, s, o);
    __syncthreads();
    if (l == 0) red[w] = s;
    __syncthreads();
    if (t == 0) {
        float tot = 0.f;
        #pragma unroll
        for (int i = 0; i < 8; ++i) tot += red[i];
        red[0] = tot;
    }
    __syncthreads();
    const float inv = 1.0f / red[0];
    uint2 o;
    o.x = pack_h2(e0 * inv, e1 * inv);
    o.y = pack_h2(e2 * inv, e3 * inv);
    p[t] = o;
}

// ---------------- launch ----------------
extern "C" void kernel_launch(void* const* d_in, const int* in_sizes, int n_in,
                              void* d_out, int out_size) {
    (void)in_sizes; (void)n_in; (void)out_size;
    const float* x      = (const float*)d_in[0];
    const float* gamma  = (const float*)d_in[1];
    const float* beta   = (const float*)d_in[2];
    const float* qkv_w  = (const float*)d_in[3];
    const float* qkv_b  = (const float*)d_in[4];
    const float* proj_w = (const float*)d_in[5];
    const float* proj_b = (const float*)d_in[6];
    const float* biases = (const float*)d_in[7];
    const int*   bidx   = (const int*)d_in[8];
    float* out = (float*)d_out;

    cudaFuncSetAttribute(mm_h<0>, cudaFuncAttributeMaxDynamicSharedMemorySize, MM_SMEM_H);
    cudaFuncSetAttribute(mm_h<2>, cudaFuncAttributeMaxDynamicSharedMemorySize, MM_SMEM_H);
    cudaFuncSetAttribute(mm_h<3>, cudaFuncAttributeMaxDynamicSharedMemorySize, MM_SMEM_H);
    cudaFuncSetAttribute(qk_wide, cudaFuncAttributeMaxDynamicSharedMemorySize, W1_SMEM);

    __half *wq_p = nullptr, *wp_p = nullptr, *av_p = nullptr;
    cudaGetSymbolAddress((void**)&wq_p, g_wq);
    cudaGetSymbolAddress((void**)&wp_p, g_wp);
    cudaGetSymbolAddress((void**)&av_p, g_av);

    ln_kernel<<<BB * NN, 128>>>(x, gamma, beta);

    transpose_half<<<dim3(QKVV / 32, DIMV / 32), 256>>>(qkv_w, wq_p, DIMV, QKVV);
    transpose_half<<<dim3(DIMV / 32, DHV / 32), 256>>>(proj_w, wp_p, DHV, DIMV);

    biasmat_kernel<<<dim3(NN * NN / 256, HH), 256>>>(biases, bidx);

    // QKV: [32768 x 512] @ [512 x 3072] -> half
    mm_h<0><<<dim3(QKVV / 128, (BB * NN) / 128), 256, MM_SMEM_H>>>(wq_p, nullptr, nullptr, qkv_b);

    // V transpose for mm2 (vectorized)
    vt_kernel<<<dim3(DV / 64, NN / 64, BB * HH), 256>>>();

    // logits per (b,h) -> g_attn (half), widened QK
    qk_wide<<<dim3(NN / 512, NN / 128, BB * HH), 256, W1_SMEM>>>();

    softmax_kernel<<<BB * HH * NN, 256>>>();

    // P @ Vt per (b,h) -> g_av half
    mm_h<2><<<dim3(DV / 128, NN / 128, BB * HH), 256, MM_SMEM_H>>>(nullptr, nullptr, nullptr, nullptr);

    // proj: [32768 x 2048] @ [2048 x 512] -> out fp32
    mm_h<3><<<dim3(DIMV / 128, (BB * NN) / 128), 256, MM_SMEM_H>>>(wp_p, av_p, out, proj_b);
}